// round 1
// baseline (speedup 1.0000x reference)
#include <cuda_runtime.h>

#define BB 2
#define SS 2048
#define DD 1024
#define HH 16
#define HD 64

// Scratch for head-split projections: [B,H,S,64] each, 16MB x3 static.
__device__ float g_Q[BB*HH*SS*HD];
__device__ float g_K[BB*HH*SS*HD];
__device__ float g_V[BB*HH*SS*HD];

// ---------------------------------------------------------------------------
// Projection: y[i][j] = sum_k X[i][k] * W[j][k] + bias[j]
// M=4096, N=1024, K=1024. 128x128 block, BK=8, 256 threads, 8x8 micro-tile.
// Writes into head-split layout dst[((b*H+h)*S + s)*64 + d].
// ---------------------------------------------------------------------------
__global__ void __launch_bounds__(256) proj_kernel(const float* __restrict__ X,
                                                   const float* __restrict__ W,
                                                   const float* __restrict__ bias,
                                                   int which)
{
    float* dst = (which == 0) ? g_Q : ((which == 1) ? g_K : g_V);

    __shared__ float As[8][128];
    __shared__ float Bs[8][128];

    const int bi = blockIdx.y * 128;
    const int bj = blockIdx.x * 128;
    const int tid = threadIdx.x;
    const int tx = tid & 15;        // 16 col-groups
    const int ty = tid >> 4;        // 16 row-groups
    const int lr = tid >> 1;        // 0..127 (load row)
    const int lc = (tid & 1) * 4;   // 0 or 4 (load k offset)

    const float* Xp = X + (size_t)(bi + lr) * DD + lc;
    const float* Wp = W + (size_t)(bj + lr) * DD + lc;

    float acc[8][8];
#pragma unroll
    for (int i = 0; i < 8; i++)
#pragma unroll
        for (int j = 0; j < 8; j++) acc[i][j] = 0.0f;

    for (int k0 = 0; k0 < DD; k0 += 8) {
        float4 a4 = *(const float4*)(Xp + k0);
        float4 w4 = *(const float4*)(Wp + k0);
        As[lc + 0][lr] = a4.x; As[lc + 1][lr] = a4.y;
        As[lc + 2][lr] = a4.z; As[lc + 3][lr] = a4.w;
        Bs[lc + 0][lr] = w4.x; Bs[lc + 1][lr] = w4.y;
        Bs[lc + 2][lr] = w4.z; Bs[lc + 3][lr] = w4.w;
        __syncthreads();

#pragma unroll
        for (int k = 0; k < 8; k++) {
            float a[8], bb[8];
            *(float4*)&a[0]  = *(const float4*)&As[k][ty * 8];
            *(float4*)&a[4]  = *(const float4*)&As[k][ty * 8 + 4];
            *(float4*)&bb[0] = *(const float4*)&Bs[k][tx * 8];
            *(float4*)&bb[4] = *(const float4*)&Bs[k][tx * 8 + 4];
#pragma unroll
            for (int i = 0; i < 8; i++)
#pragma unroll
                for (int j = 0; j < 8; j++)
                    acc[i][j] = fmaf(a[i], bb[j], acc[i][j]);
        }
        __syncthreads();
    }

    // Epilogue: add bias, scatter into head-split layout.
#pragma unroll
    for (int ii = 0; ii < 8; ii++) {
        const int i = bi + ty * 8 + ii;
        const int b = i >> 11;          // i / S
        const int s = i & 2047;         // i % S
#pragma unroll
        for (int jj = 0; jj < 8; jj++) {
            const int j = bj + tx * 8 + jj;
            const int h = j >> 6;
            const int d = j & 63;
            dst[(((size_t)(b * HH + h)) * SS + s) * HD + d] = acc[ii][jj] + bias[j];
        }
    }
}

// ---------------------------------------------------------------------------
// Fused attention per (b, h, 16-row q-block).
//   Phase 1: scores[16][2048] = 1/(8 * Q Kt) computed in 256-col chunks.
//   Phase 2: softmax per row (warp-per-row).
//   Phase 3: attn_mean += attn/H via red.global.add.f32.
//   Phase 4: out = attn @ V (4-way k-split, smem reduce), direct store.
// SMEM: sc 16x2048 (128KB) | kv 17408 f (K^T [64][256] / V [256][68]) |
//       qt [64][16] | red [4][16][64]   => 221184 bytes dynamic.
// ---------------------------------------------------------------------------
#define SMEM_FLOATS (32768 + 17408 + 1024 + 4096)
#define SMEM_BYTES  (SMEM_FLOATS * 4)

__global__ void __launch_bounds__(256) attn_kernel(float* __restrict__ out)
{
    extern __shared__ float sm[];
    float* sc  = sm;                      // scores / attn, [16][2048]
    float* kv  = sm + 32768;              // K^T chunk [64][256]  or V chunk [256][68]
    float* qt  = sm + 32768 + 17408;      // Q^T [64][16]
    float* red = qt + 1024;               // [4][16][64]

    const int cta = blockIdx.x;           // b*2048 + h*128 + qb
    const int qb  = cta & 127;
    const int h   = (cta >> 7) & 15;
    const int b   = cta >> 11;
    const int q0  = qb * 16;
    const int tid = threadIdx.x;

    const float* Qg = g_Q + ((size_t)(b * HH + h) * SS + q0) * HD;
    const float* Kg = g_K + (size_t)(b * HH + h) * SS * HD;
    const float* Vg = g_V + (size_t)(b * HH + h) * SS * HD;

    // Load Q tile transposed: qt[d][r]
    {
        const int r  = tid >> 4;
        const int c4 = (tid & 15) * 4;
        float4 v = *(const float4*)&Qg[r * HD + c4];
        qt[(c4 + 0) * 16 + r] = v.x;
        qt[(c4 + 1) * 16 + r] = v.y;
        qt[(c4 + 2) * 16 + r] = v.z;
        qt[(c4 + 3) * 16 + r] = v.w;
    }

    // ---- Phase 1: scores = 1 / (8 * Q K^T) ----
    const int rg = tid >> 6;    // 0..3  -> q rows rg*4..rg*4+3
    const int cg = tid & 63;    // 0..63 -> k cols cg*4..cg*4+3
    const int r0 = rg * 4;

    for (int kc = 0; kc < 8; kc++) {
        // Load 256 K rows, transposed: kv[d][kk]
        const float* Krow = Kg + (size_t)(kc * 256 + tid) * HD;
#pragma unroll
        for (int d4 = 0; d4 < 16; d4++) {
            float4 v = *(const float4*)&Krow[d4 * 4];
            kv[(d4 * 4 + 0) * 256 + tid] = v.x;
            kv[(d4 * 4 + 1) * 256 + tid] = v.y;
            kv[(d4 * 4 + 2) * 256 + tid] = v.z;
            kv[(d4 * 4 + 3) * 256 + tid] = v.w;
        }
        __syncthreads();

        float acc[4][4];
#pragma unroll
        for (int i = 0; i < 4; i++)
#pragma unroll
            for (int j = 0; j < 4; j++) acc[i][j] = 0.0f;

#pragma unroll 8
        for (int d = 0; d < 64; d++) {
            float qv[4], kvv[4];
            *(float4*)qv  = *(const float4*)&qt[d * 16 + r0];
            *(float4*)kvv = *(const float4*)&kv[d * 256 + cg * 4];
#pragma unroll
            for (int i = 0; i < 4; i++)
#pragma unroll
                for (int j = 0; j < 4; j++)
                    acc[i][j] = fmaf(qv[i], kvv[j], acc[i][j]);
        }

#pragma unroll
        for (int i = 0; i < 4; i++) {
            float4 sv;
            sv.x = __fdividef(1.0f, 8.0f * acc[i][0]);
            sv.y = __fdividef(1.0f, 8.0f * acc[i][1]);
            sv.z = __fdividef(1.0f, 8.0f * acc[i][2]);
            sv.w = __fdividef(1.0f, 8.0f * acc[i][3]);
            *(float4*)&sc[(r0 + i) * 2048 + kc * 256 + cg * 4] = sv;
        }
        __syncthreads();  // everyone done with kv before next chunk / softmax
    }

    // ---- Phase 2: softmax per row (one warp per row, 2 rows per warp) ----
    {
        const int warp = tid >> 5;
        const int lane = tid & 31;
        for (int rr = warp; rr < 16; rr += 8) {
            float* row = sc + rr * 2048;
            float m = -3.4e38f;
            for (int k = lane; k < 2048; k += 32) m = fmaxf(m, row[k]);
#pragma unroll
            for (int o = 16; o; o >>= 1) m = fmaxf(m, __shfl_xor_sync(0xffffffffu, m, o));
            float ssum = 0.0f;
            for (int k = lane; k < 2048; k += 32) {
                float e = __expf(row[k] - m);
                row[k] = e;
                ssum += e;
            }
#pragma unroll
            for (int o = 16; o; o >>= 1) ssum += __shfl_xor_sync(0xffffffffu, ssum, o);
            const float inv = __fdividef(1.0f, ssum);
            for (int k = lane; k < 2048; k += 32) row[k] *= inv;
        }
    }
    __syncthreads();

    // ---- Phase 3: attn_mean += attn / H ----
    {
        float* am = out + (size_t)BB * SS * DD;
        for (int idx = tid; idx < 16 * 2048; idx += 256) {
            const int rr = idx >> 11;
            const int kk = idx & 2047;
            atomicAdd(&am[((size_t)(b * SS + q0 + rr)) * SS + kk],
                      sc[idx] * 0.0625f);
        }
    }

    // ---- Phase 4: out = attn @ V ----
    {
        const int dg  = tid & 15;          // 16 d-groups of 4
        const int rg2 = (tid >> 4) & 3;    // 4 row-groups of 4
        const int kg  = tid >> 6;          // 4 k-split groups
        const int rr0 = rg2 * 4;

        float acc2[4][4];
#pragma unroll
        for (int i = 0; i < 4; i++)
#pragma unroll
            for (int j = 0; j < 4; j++) acc2[i][j] = 0.0f;

        for (int vc = 0; vc < 8; vc++) {
            // Load V chunk [256][64] with row pad 68 to kill bank conflicts.
            const float* Vrow = Vg + (size_t)(vc * 256 + tid) * HD;
#pragma unroll
            for (int d4 = 0; d4 < 16; d4++) {
                float4 v = *(const float4*)&Vrow[d4 * 4];
                *(float4*)&kv[tid * 68 + d4 * 4] = v;
            }
            __syncthreads();

            const float* scb = sc + vc * 256;
#pragma unroll 4
            for (int kk2 = 0; kk2 < 64; kk2++) {
                const int k = kg * 64 + kk2;
                float vv[4];
                *(float4*)vv = *(const float4*)&kv[k * 68 + dg * 4];
                float a0 = scb[(rr0 + 0) * 2048 + k];
                float a1 = scb[(rr0 + 1) * 2048 + k];
                float a2 = scb[(rr0 + 2) * 2048 + k];
                float a3 = scb[(rr0 + 3) * 2048 + k];
#pragma unroll
                for (int j = 0; j < 4; j++) {
                    acc2[0][j] = fmaf(a0, vv[j], acc2[0][j]);
                    acc2[1][j] = fmaf(a1, vv[j], acc2[1][j]);
                    acc2[2][j] = fmaf(a2, vv[j], acc2[2][j]);
                    acc2[3][j] = fmaf(a3, vv[j], acc2[3][j]);
                }
            }
            __syncthreads();
        }

        // Cross-kg reduction via smem.
#pragma unroll
        for (int i = 0; i < 4; i++) {
            float4 v = make_float4(acc2[i][0], acc2[i][1], acc2[i][2], acc2[i][3]);
            *(float4*)&red[(kg * 16 + rr0 + i) * 64 + dg * 4] = v;
        }
        __syncthreads();

        for (int e = tid; e < 16 * 64; e += 256) {
            const int r = e >> 6;
            const int d = e & 63;
            float v = red[r * 64 + d] + red[(16 + r) * 64 + d]
                    + red[(32 + r) * 64 + d] + red[(48 + r) * 64 + d];
            out[((size_t)(b * SS + q0 + r)) * DD + h * HD + d] = v;
        }
    }
}

// ---------------------------------------------------------------------------
extern "C" void kernel_launch(void* const* d_in, const int* in_sizes, int n_in,
                              void* d_out, int out_size)
{
    const float* query = (const float*)d_in[0];
    const float* key_  = (const float*)d_in[1];
    const float* value = (const float*)d_in[2];
    const float* Wq    = (const float*)d_in[3];
    const float* bq    = (const float*)d_in[4];
    const float* Wk    = (const float*)d_in[5];
    const float* bk    = (const float*)d_in[6];
    const float* Wv    = (const float*)d_in[7];
    const float* bv    = (const float*)d_in[8];
    float* out = (float*)d_out;

    // Zero the attn_mean accumulation region (after the [B,S,D] out block).
    cudaMemsetAsync(out + (size_t)BB * SS * DD, 0,
                    (size_t)BB * SS * SS * sizeof(float));

    dim3 pg(DD / 128, (BB * SS) / 128);
    proj_kernel<<<pg, 256>>>(query, Wq, bq, 0);
    proj_kernel<<<pg, 256>>>(key_,  Wk, bk, 1);
    proj_kernel<<<pg, 256>>>(value, Wv, bv, 2);

    cudaFuncSetAttribute(attn_kernel,
                         cudaFuncAttributeMaxDynamicSharedMemorySize, SMEM_BYTES);
    attn_kernel<<<BB * HH * (SS / 16), 256, SMEM_BYTES>>>(out);
}